// round 2
// baseline (speedup 1.0000x reference)
#include <cuda_runtime.h>

#define Bsz 4
#define Nn  65536
#define Kk  16
#define Dd  16
#define NK  (Nn * Kk)            // 1048576 = 2^20
#define Ptot (Bsz * NK)          // 4194304

// Scratch (allocation-free rule: __device__ globals)
__device__ float  g_featT[(size_t)Bsz * Nn * Dd];   // (B, N, D) transposed features, 16MB
__device__ double g_M[35];                          // 7 first + 28 upper-tri second moments
__device__ float4 g_c1[16];                         // per-channel (W0, A.x, A.y, A.z) * scale
__device__ float4 g_c2[16];                         // per-channel (B.x, B.y, B.z, shift)

// ---------------------------------------------------------------------------
// Kernel 0: transpose features (B, D, N) -> (B, N, D), and zero g_M
// ---------------------------------------------------------------------------
__global__ void k_transpose(const float* __restrict__ feats) {
    __shared__ float tile[16][129];
    int blk = blockIdx.x;                 // 2048 blocks: 4 batches * 512 tiles
    int b   = blk >> 9;
    int n0  = (blk & 511) * 128;
    int tid = threadIdx.x;                // 256 threads

    if (blk == 0 && tid < 35) g_M[tid] = 0.0;

    int nn = tid & 127;
    int dd = tid >> 7;                    // 0..1
#pragma unroll
    for (int it = 0; it < 8; it++) {
        int d = dd + it * 2;
        tile[d][nn] = feats[((size_t)(b * 16 + d)) * Nn + n0 + nn];
    }
    __syncthreads();

    int d2 = tid & 15;
    int nb = tid >> 4;                    // 0..15
#pragma unroll
    for (int it = 0; it < 8; it++) {
        int nn2 = nb + it * 16;
        g_featT[((size_t)b * Nn + n0 + nn2) * 16 + d2] = tile[d2][nn2];
    }
}

// ---------------------------------------------------------------------------
// Kernel 1: accumulate moments of r7 = [dist, ext(3), nbr(3)]
// ---------------------------------------------------------------------------
__global__ void k_stats(const float* __restrict__ coords,
                        const int* __restrict__ idx) {
    float acc[35];
#pragma unroll
    for (int i = 0; i < 35; i++) acc[i] = 0.f;

    int stride = gridDim.x * blockDim.x;
    for (int p = blockIdx.x * blockDim.x + threadIdx.x; p < Ptot; p += stride) {
        int b = p >> 20;
        int n = (p >> 4) & (Nn - 1);
        int j = idx[p];
        const float* cc = coords + ((size_t)b * Nn + n) * 3;
        const float* nc = coords + ((size_t)b * Nn + j) * 3;
        float r[7];
        float ex = cc[0], ey = cc[1], ez = cc[2];
        float nx = __ldg(nc), ny = __ldg(nc + 1), nz = __ldg(nc + 2);
        float rx = ex - nx, ry = ey - ny, rz = ez - nz;
        r[0] = sqrtf(rx * rx + ry * ry + rz * rz);
        r[1] = ex; r[2] = ey; r[3] = ez;
        r[4] = nx; r[5] = ny; r[6] = nz;
#pragma unroll
        for (int i = 0; i < 7; i++) acc[i] += r[i];
        int c = 7;
#pragma unroll
        for (int i = 0; i < 7; i++)
#pragma unroll
            for (int q = i; q < 7; q++) acc[c++] += r[i] * r[q];
    }

    // warp reduce all 35
#pragma unroll
    for (int i = 0; i < 35; i++)
        for (int off = 16; off; off >>= 1)
            acc[i] += __shfl_down_sync(0xffffffffu, acc[i], off);

    __shared__ float s[8][35];
    int lane = threadIdx.x & 31, w = threadIdx.x >> 5;
    if (lane == 0) {
#pragma unroll
        for (int i = 0; i < 35; i++) s[w][i] = acc[i];
    }
    __syncthreads();
    if (threadIdx.x < 35) {
        float t = 0.f;
#pragma unroll
        for (int w2 = 0; w2 < 8; w2++) t += s[w2][threadIdx.x];
        atomicAdd(&g_M[threadIdx.x], (double)t);
    }
}

// ---------------------------------------------------------------------------
// Kernel 2: analytic BN stats per output channel, fold into conv coefficients
// x_o = W0*dist + (Wrel+Wext).ext + (Wnbr-Wrel).nbr + bias
// ---------------------------------------------------------------------------
__device__ __forceinline__ int tri_idx(int i, int j) {  // i <= j
    return i * 7 - i * (i - 1) / 2 + (j - i);
}

__global__ void k_finalize(const float* __restrict__ W, const float* __restrict__ bias,
                           const float* __restrict__ gamma, const float* __restrict__ beta) {
    int o = threadIdx.x;
    if (o >= 16) return;
    const double invP = 1.0 / (double)Ptot;
    double m[7];
#pragma unroll
    for (int i = 0; i < 7; i++) m[i] = g_M[i] * invP;

    double a[7];
    a[0] = (double)W[o * 10 + 0];
#pragma unroll
    for (int i = 0; i < 3; i++) a[1 + i] = (double)W[o * 10 + 1 + i] + (double)W[o * 10 + 4 + i];
#pragma unroll
    for (int i = 0; i < 3; i++) a[4 + i] = (double)W[o * 10 + 7 + i] - (double)W[o * 10 + 1 + i];

    double mean = (double)bias[o];
#pragma unroll
    for (int i = 0; i < 7; i++) mean += a[i] * m[i];

    double var = 0.0;
    for (int i = 0; i < 7; i++)
        for (int j = 0; j < 7; j++) {
            int ii = i < j ? i : j, jj = i < j ? j : i;
            double C = g_M[7 + tri_idx(ii, jj)] * invP - m[i] * m[j];
            var += a[i] * a[j] * C;
        }

    double scale = (double)gamma[o] * rsqrt(var + 1e-6);
    double shift = (double)beta[o] + ((double)bias[o] - mean) * scale;
    g_c1[o] = make_float4((float)(a[0] * scale), (float)(a[1] * scale),
                          (float)(a[2] * scale), (float)(a[3] * scale));
    g_c2[o] = make_float4((float)(a[4] * scale), (float)(a[5] * scale),
                          (float)(a[6] * scale), (float)shift);
}

// ---------------------------------------------------------------------------
// Kernel 3: main — 4 points (half a K-row) per thread, float4 stores per channel
// ---------------------------------------------------------------------------
__global__ void k_main(const float* __restrict__ coords,
                       const int* __restrict__ idx,
                       float* __restrict__ out) {
    __shared__ float4 sc1[16], sc2[16];
    if (threadIdx.x < 16) { sc1[threadIdx.x] = g_c1[threadIdx.x]; sc2[threadIdx.x] = g_c2[threadIdx.x]; }
    __syncthreads();

    int t  = blockIdx.x * blockDim.x + threadIdx.x;   // 0 .. Ptot/4-1
    int p0 = t << 2;
    int b  = p0 >> 20;
    int n  = (p0 >> 4) & (Nn - 1);
    int k0 = p0 & 15;                                  // 0, 4, 8, 12

    int4 jj = ((const int4*)idx)[t];

    const float* cc = coords + ((size_t)b * Nn + n) * 3;
    float ex = cc[0], ey = cc[1], ez = cc[2];

    const float* base = coords + (size_t)b * Nn * 3;
    const float* nc0 = base + (size_t)jj.x * 3;
    const float* nc1 = base + (size_t)jj.y * 3;
    const float* nc2 = base + (size_t)jj.z * 3;
    const float* nc3 = base + (size_t)jj.w * 3;
    float nx0 = __ldg(nc0), ny0 = __ldg(nc0 + 1), nz0 = __ldg(nc0 + 2);
    float nx1 = __ldg(nc1), ny1 = __ldg(nc1 + 1), nz1 = __ldg(nc1 + 2);
    float nx2 = __ldg(nc2), ny2 = __ldg(nc2 + 1), nz2 = __ldg(nc2 + 2);
    float nx3 = __ldg(nc3), ny3 = __ldg(nc3 + 1), nz3 = __ldg(nc3 + 2);

    float rx, ry, rz;
    rx = ex - nx0; ry = ey - ny0; rz = ez - nz0;
    float d0 = sqrtf(rx * rx + ry * ry + rz * rz);
    rx = ex - nx1; ry = ey - ny1; rz = ez - nz1;
    float d1 = sqrtf(rx * rx + ry * ry + rz * rz);
    rx = ex - nx2; ry = ey - ny2; rz = ez - nz2;
    float d2 = sqrtf(rx * rx + ry * ry + rz * rz);
    rx = ex - nx3; ry = ey - ny3; rz = ez - nz3;
    float d3 = sqrtf(rx * rx + ry * ry + rz * rz);

    const float* fb = g_featT + (size_t)b * Nn * 16;
    const float4* f0 = (const float4*)(fb + (size_t)jj.x * 16);
    const float4* f1 = (const float4*)(fb + (size_t)jj.y * 16);
    const float4* f2 = (const float4*)(fb + (size_t)jj.z * 16);
    const float4* f3 = (const float4*)(fb + (size_t)jj.w * 16);

    float* o = out + (size_t)b * 32 * NK + (size_t)n * 16 + k0;
#pragma unroll
    for (int q = 0; q < 4; q++) {
        float4 A = f0[q], B = f1[q], C = f2[q], E = f3[q];
        *(float4*)(o + (size_t)(4 * q + 0) * NK) = make_float4(A.x, B.x, C.x, E.x);
        *(float4*)(o + (size_t)(4 * q + 1) * NK) = make_float4(A.y, B.y, C.y, E.y);
        *(float4*)(o + (size_t)(4 * q + 2) * NK) = make_float4(A.z, B.z, C.z, E.z);
        *(float4*)(o + (size_t)(4 * q + 3) * NK) = make_float4(A.w, B.w, C.w, E.w);
    }

    float* o2 = o + (size_t)16 * NK;
#pragma unroll
    for (int d = 0; d < 16; d++) {
        float4 c1 = sc1[d], c2 = sc2[d];
        float ecom = fmaf(c1.y, ex, fmaf(c1.z, ey, fmaf(c1.w, ez, c2.w)));
        float v0 = fmaf(c1.x, d0, fmaf(c2.x, nx0, fmaf(c2.y, ny0, fmaf(c2.z, nz0, ecom))));
        float v1 = fmaf(c1.x, d1, fmaf(c2.x, nx1, fmaf(c2.y, ny1, fmaf(c2.z, nz1, ecom))));
        float v2 = fmaf(c1.x, d2, fmaf(c2.x, nx2, fmaf(c2.y, ny2, fmaf(c2.z, nz2, ecom))));
        float v3 = fmaf(c1.x, d3, fmaf(c2.x, nx3, fmaf(c2.y, ny3, fmaf(c2.z, nz3, ecom))));
        *(float4*)(o2 + (size_t)d * NK) =
            make_float4(fmaxf(v0, 0.f), fmaxf(v1, 0.f), fmaxf(v2, 0.f), fmaxf(v3, 0.f));
    }
}

// ---------------------------------------------------------------------------
extern "C" void kernel_launch(void* const* d_in, const int* in_sizes, int n_in,
                              void* d_out, int out_size) {
    const float* coords = (const float*)d_in[0];
    const float* feats  = (const float*)d_in[1];
    const int*   idx    = (const int*)d_in[2];
    const float* W      = (const float*)d_in[3];
    const float* bias   = (const float*)d_in[4];
    const float* gamma  = (const float*)d_in[5];
    const float* beta   = (const float*)d_in[6];
    float*       out    = (float*)d_out;

    k_transpose<<<Bsz * (Nn / 128), 256>>>(feats);
    k_stats<<<2048, 256>>>(coords, idx);
    k_finalize<<<1, 32>>>(W, bias, gamma, beta);
    k_main<<<(Ptot / 4) / 256, 256>>>(coords, idx, out);
}

// round 3
// speedup vs baseline: 1.1124x; 1.1124x over previous
#include <cuda_runtime.h>

#define Bsz 4
#define Nn  65536
#define Kk  16
#define Dd  16
#define NK  (Nn * Kk)            // 1048576 = 2^20
#define Ptot (Bsz * NK)          // 4194304

// Scratch (allocation-free rule: __device__ globals)
__device__ float  g_featT[(size_t)Bsz * Nn * Dd];   // (B, N, D) transposed features, 16MB
__device__ float4 g_coordsPad[(size_t)Bsz * Nn];    // (B, N, 4) padded coords, 4MB
__device__ double g_M[35];                          // 7 first + 28 upper-tri second moments
__device__ float4 g_c1[16];                         // per-channel (W0, A.x, A.y, A.z) * scale
__device__ float4 g_c2[16];                         // per-channel (B.x, B.y, B.z, shift)

// ---------------------------------------------------------------------------
// Kernel 0: transpose features (B,D,N)->(B,N,D), pad coords to float4, zero g_M
// ---------------------------------------------------------------------------
__global__ void k_prep(const float* __restrict__ feats,
                       const float* __restrict__ coords) {
    __shared__ float tile[16][129];
    int blk = blockIdx.x;                 // 2048 blocks: 4 batches * 512 tiles
    int b   = blk >> 9;
    int n0  = (blk & 511) * 128;
    int tid = threadIdx.x;                // 256 threads

    if (blk == 0 && tid < 35) g_M[tid] = 0.0;

    // pad coords for this tile's 128 points (threads 0..127)
    if (tid < 128) {
        int n = n0 + tid;
        const float* c = coords + ((size_t)b * Nn + n) * 3;
        g_coordsPad[(size_t)b * Nn + n] = make_float4(c[0], c[1], c[2], 0.f);
    }

    int nn = tid & 127;
    int dd = tid >> 7;                    // 0..1
#pragma unroll
    for (int it = 0; it < 8; it++) {
        int d = dd + it * 2;
        tile[d][nn] = feats[((size_t)(b * 16 + d)) * Nn + n0 + nn];
    }
    __syncthreads();

    int d2 = tid & 15;
    int nb = tid >> 4;                    // 0..15
#pragma unroll
    for (int it = 0; it < 8; it++) {
        int nn2 = nb + it * 16;
        g_featT[((size_t)b * Nn + n0 + nn2) * 16 + d2] = tile[d2][nn2];
    }
}

// ---------------------------------------------------------------------------
// Kernel 1: accumulate moments of r7 = [dist, ext(3), nbr(3)]
// ---------------------------------------------------------------------------
__global__ void k_stats(const int* __restrict__ idx) {
    float acc[35];
#pragma unroll
    for (int i = 0; i < 35; i++) acc[i] = 0.f;

    int stride = gridDim.x * blockDim.x;
    for (int p = blockIdx.x * blockDim.x + threadIdx.x; p < Ptot; p += stride) {
        int b = p >> 20;
        int n = (p >> 4) & (Nn - 1);
        int j = idx[p];
        const float4* cb = g_coordsPad + (size_t)b * Nn;
        float4 ce = __ldg(cb + n);
        float4 cn = __ldg(cb + j);
        float r[7];
        float rx = ce.x - cn.x, ry = ce.y - cn.y, rz = ce.z - cn.z;
        r[0] = sqrtf(rx * rx + ry * ry + rz * rz);
        r[1] = ce.x; r[2] = ce.y; r[3] = ce.z;
        r[4] = cn.x; r[5] = cn.y; r[6] = cn.z;
#pragma unroll
        for (int i = 0; i < 7; i++) acc[i] += r[i];
        int c = 7;
#pragma unroll
        for (int i = 0; i < 7; i++)
#pragma unroll
            for (int q = i; q < 7; q++) acc[c++] += r[i] * r[q];
    }

    // warp reduce all 35
#pragma unroll
    for (int i = 0; i < 35; i++)
        for (int off = 16; off; off >>= 1)
            acc[i] += __shfl_down_sync(0xffffffffu, acc[i], off);

    __shared__ float s[8][35];
    int lane = threadIdx.x & 31, w = threadIdx.x >> 5;
    if (lane == 0) {
#pragma unroll
        for (int i = 0; i < 35; i++) s[w][i] = acc[i];
    }
    __syncthreads();
    if (threadIdx.x < 35) {
        float t = 0.f;
#pragma unroll
        for (int w2 = 0; w2 < 8; w2++) t += s[w2][threadIdx.x];
        atomicAdd(&g_M[threadIdx.x], (double)t);
    }
}

// ---------------------------------------------------------------------------
// Kernel 2: analytic BN stats per output channel, fold into conv coefficients
// x_o = W0*dist + (Wrel+Wext).ext + (Wnbr-Wrel).nbr + bias
// ---------------------------------------------------------------------------
__device__ __forceinline__ int tri_idx(int i, int j) {  // i <= j
    return i * 7 - i * (i - 1) / 2 + (j - i);
}

__global__ void k_finalize(const float* __restrict__ W, const float* __restrict__ bias,
                           const float* __restrict__ gamma, const float* __restrict__ beta) {
    int o = threadIdx.x;
    if (o >= 16) return;
    const double invP = 1.0 / (double)Ptot;
    double m[7];
#pragma unroll
    for (int i = 0; i < 7; i++) m[i] = g_M[i] * invP;

    double a[7];
    a[0] = (double)W[o * 10 + 0];
#pragma unroll
    for (int i = 0; i < 3; i++) a[1 + i] = (double)W[o * 10 + 1 + i] + (double)W[o * 10 + 4 + i];
#pragma unroll
    for (int i = 0; i < 3; i++) a[4 + i] = (double)W[o * 10 + 7 + i] - (double)W[o * 10 + 1 + i];

    double mean = (double)bias[o];
#pragma unroll
    for (int i = 0; i < 7; i++) mean += a[i] * m[i];

    double var = 0.0;
    for (int i = 0; i < 7; i++)
        for (int j = 0; j < 7; j++) {
            int ii = i < j ? i : j, jj = i < j ? j : i;
            double C = g_M[7 + tri_idx(ii, jj)] * invP - m[i] * m[j];
            var += a[i] * a[j] * C;
        }

    double scale = (double)gamma[o] * rsqrt(var + 1e-6);
    double shift = (double)beta[o] + ((double)bias[o] - mean) * scale;
    g_c1[o] = make_float4((float)(a[0] * scale), (float)(a[1] * scale),
                          (float)(a[2] * scale), (float)(a[3] * scale));
    g_c2[o] = make_float4((float)(a[4] * scale), (float)(a[5] * scale),
                          (float)(a[6] * scale), (float)shift);
}

// ---------------------------------------------------------------------------
// Kernel 3: main — 4 points (half a K-row) per thread, float4 I/O throughout
// ---------------------------------------------------------------------------
__global__ void __launch_bounds__(256)
k_main(const int* __restrict__ idx, float* __restrict__ out) {
    __shared__ float4 sc1[16], sc2[16];
    if (threadIdx.x < 16) { sc1[threadIdx.x] = g_c1[threadIdx.x]; sc2[threadIdx.x] = g_c2[threadIdx.x]; }
    __syncthreads();

    int t  = blockIdx.x * blockDim.x + threadIdx.x;   // 0 .. Ptot/4-1
    int p0 = t << 2;
    int b  = p0 >> 20;
    int n  = (p0 >> 4) & (Nn - 1);
    int k0 = p0 & 15;                                  // 0, 4, 8, 12

    int4 jj = ((const int4*)idx)[t];

    const float4* cb = g_coordsPad + (size_t)b * Nn;
    float4 ce = __ldg(cb + n);
    float4 c0 = __ldg(cb + jj.x);
    float4 c1 = __ldg(cb + jj.y);
    float4 c2 = __ldg(cb + jj.z);
    float4 c3 = __ldg(cb + jj.w);

    float rx, ry, rz;
    rx = ce.x - c0.x; ry = ce.y - c0.y; rz = ce.z - c0.z;
    float d0 = sqrtf(rx * rx + ry * ry + rz * rz);
    rx = ce.x - c1.x; ry = ce.y - c1.y; rz = ce.z - c1.z;
    float d1 = sqrtf(rx * rx + ry * ry + rz * rz);
    rx = ce.x - c2.x; ry = ce.y - c2.y; rz = ce.z - c2.z;
    float d2 = sqrtf(rx * rx + ry * ry + rz * rz);
    rx = ce.x - c3.x; ry = ce.y - c3.y; rz = ce.z - c3.z;
    float d3 = sqrtf(rx * rx + ry * ry + rz * rz);

    const float* fb = g_featT + (size_t)b * Nn * 16;
    const float4* f0 = (const float4*)(fb + (size_t)jj.x * 16);
    const float4* f1 = (const float4*)(fb + (size_t)jj.y * 16);
    const float4* f2 = (const float4*)(fb + (size_t)jj.z * 16);
    const float4* f3 = (const float4*)(fb + (size_t)jj.w * 16);

    float* o = out + (size_t)b * 32 * NK + (size_t)n * 16 + k0;
#pragma unroll
    for (int q = 0; q < 4; q++) {
        float4 A = __ldg(f0 + q), B = __ldg(f1 + q), C = __ldg(f2 + q), E = __ldg(f3 + q);
        __stcs((float4*)(o + (size_t)(4 * q + 0) * NK), make_float4(A.x, B.x, C.x, E.x));
        __stcs((float4*)(o + (size_t)(4 * q + 1) * NK), make_float4(A.y, B.y, C.y, E.y));
        __stcs((float4*)(o + (size_t)(4 * q + 2) * NK), make_float4(A.z, B.z, C.z, E.z));
        __stcs((float4*)(o + (size_t)(4 * q + 3) * NK), make_float4(A.w, B.w, C.w, E.w));
    }

    float* o2 = o + (size_t)16 * NK;
#pragma unroll
    for (int d = 0; d < 16; d++) {
        float4 w1 = sc1[d], w2 = sc2[d];
        float ecom = fmaf(w1.y, ce.x, fmaf(w1.z, ce.y, fmaf(w1.w, ce.z, w2.w)));
        float v0 = fmaf(w1.x, d0, fmaf(w2.x, c0.x, fmaf(w2.y, c0.y, fmaf(w2.z, c0.z, ecom))));
        float v1 = fmaf(w1.x, d1, fmaf(w2.x, c1.x, fmaf(w2.y, c1.y, fmaf(w2.z, c1.z, ecom))));
        float v2 = fmaf(w1.x, d2, fmaf(w2.x, c2.x, fmaf(w2.y, c2.y, fmaf(w2.z, c2.z, ecom))));
        float v3 = fmaf(w1.x, d3, fmaf(w2.x, c3.x, fmaf(w2.y, c3.y, fmaf(w2.z, c3.z, ecom))));
        __stcs((float4*)(o2 + (size_t)d * NK),
               make_float4(fmaxf(v0, 0.f), fmaxf(v1, 0.f), fmaxf(v2, 0.f), fmaxf(v3, 0.f)));
    }
}

// ---------------------------------------------------------------------------
extern "C" void kernel_launch(void* const* d_in, const int* in_sizes, int n_in,
                              void* d_out, int out_size) {
    const float* coords = (const float*)d_in[0];
    const float* feats  = (const float*)d_in[1];
    const int*   idx    = (const int*)d_in[2];
    const float* W      = (const float*)d_in[3];
    const float* bias   = (const float*)d_in[4];
    const float* gamma  = (const float*)d_in[5];
    const float* beta   = (const float*)d_in[6];
    float*       out    = (float*)d_out;

    k_prep<<<Bsz * (Nn / 128), 256>>>(feats, coords);
    k_stats<<<2048, 256>>>(idx);
    k_finalize<<<1, 32>>>(W, bias, gamma, beta);
    k_main<<<(Ptot / 4) / 256, 256>>>(idx, out);
}